// round 10
// baseline (speedup 1.0000x reference)
#include <cuda_runtime.h>
#include <math.h>
#include <stdint.h>

#define B_ 32
#define L_ 256
#define A_ 20
#define NTHR 320            // 10 warps, all consumers (warp0 += pair, warp1 += const)
#define TS 16               // tiles per stage
#define NST 4               // stages per CTA (64 tiles per quarter)

__device__ float g_lg[L_][4][662];        // per (i,q): 640 acc, 20 const, pair, reg
__device__ unsigned int g_icount[L_];     // per-i arrival counters (self-reset)
__device__ unsigned int g_bcount = 0;     // combiner counter (self-reset)
__device__ double g_res[L_][3];           // per-i {lse_sum, pair_sum, reg_sum}

// smem layout (bytes):
//   0     .. 53760  buf: 2 halves x 16 tiles x 420 floats (stride-21 padded rows)
//   53760 .. 55808  xpk uint32[4 s][32 b][4 g]: bytes 4*x[b][p]
//   55808 .. 55936  xi[32]
//   55936 .. 56016  wsrow[20]
//   56016 .. 56096  csts[20]
//   56096 .. 56136  sredr[10]
//   56136 .. 56140  pairv
//   56140 .. 56148  flags[2]
// combiner reuse: lgbuf f32[32*21] @0, dred double[40] @4096
#define SMEM_BYTES 56148

__global__ __launch_bounds__(NTHR, 4) void mrf_kernel(const int* __restrict__ x,
                                                      const float* __restrict__ ws,
                                                      const float* __restrict__ wp,
                                                      float* __restrict__ out) {
    extern __shared__ char smem_raw[];
    float*        buf   = reinterpret_cast<float*>(smem_raw);
    uint32_t*     xpk   = reinterpret_cast<uint32_t*>(smem_raw + 53760);
    int*          xi    = reinterpret_cast<int*>(smem_raw + 55808);
    float*        wsrow = reinterpret_cast<float*>(smem_raw + 55936);
    float*        csts  = reinterpret_cast<float*>(smem_raw + 56016);
    float*        sredr = reinterpret_cast<float*>(smem_raw + 56096);
    float*        pairv = reinterpret_cast<float*>(smem_raw + 56136);
    int*          flags = reinterpret_cast<int*>(smem_raw + 56140);

    const int i    = blockIdx.x;
    const int q    = blockIdx.y;
    const int tid  = threadIdx.x;
    const int wid  = tid >> 5;
    const int lane = tid & 31;

    // Stage-0 prefetch first (hide behind prologue).
    const float4* wp4 = reinterpret_cast<const float4*>(wp);
    const int base4 = i * 25600 + q * 6400;   // float4 units
    float4 v[5];
#pragma unroll
    for (int w = 0; w < 5; w++) v[w] = wp4[base4 + tid + w * 320];

    // Pack x bytes (pre-scaled by 4): xpk[s*128 + b*4 + g] = 4*x[b][q*64+s*16+4g..+3]
    const int4* x4 = reinterpret_cast<const int4*>(x);
    for (int n = tid; n < 512; n += NTHR) {
        int s = n >> 7, rem = n & 127;
        int b = rem >> 2, g = rem & 3;
        int4 qq = x4[b * 64 + q * 16 + s * 4 + g];
        xpk[n] = (uint32_t)(qq.x << 2) | ((uint32_t)(qq.y << 2) << 8) |
                 ((uint32_t)(qq.z << 2) << 16) | ((uint32_t)(qq.w << 2) << 24);
    }
    if (tid < B_) xi[tid] = x[tid * L_ + i];
    if (tid >= 32 && tid < 52) wsrow[tid - 32] = ws[i * A_ + (tid - 32)];

    // Stage-invariant padded STS offsets (4 x STS.32 each).
    int dsto[5];
#pragma unroll
    for (int w = 0; w < 5; w++) {
        int slot = tid + w * 320;       // float4 slot 0..1599
        int f  = slot * 4;
        int t  = f / 400;
        int r  = f - t * 400;
        int jj = r / 20;
        int ee = r - jj * 20;           // multiple of 4, <= 16
        dsto[w] = t * 420 + jj * 21 + ee;
    }

    const int b0  = tid / 20;           // 0..15
    const int j   = tid - b0 * 20;
    const int b1  = b0 + 16;
    const int j84 = j * 84;             // byte offset of row j (21 floats)
    __syncthreads();
    const int xi84 = (wid == 0) ? xi[lane] * 84 : 0;

    float acc0 = 0.f, acc1 = 0.f, pair = 0.f, c_acc = 0.f, reg1 = 0.f, reg2 = 0.f;
    const uint4* xpk4 = reinterpret_cast<const uint4*>(xpk);

    for (int s = 0; s < NST; s++) {
        const int hofs = (s & 1) * 6720;
        // Fold reg terms from registers, then STS padded.
#pragma unroll
        for (int w = 0; w < 5; w++) {
            float4 qv = v[w];
            reg1 += fabsf(qv.x); reg2 = fmaf(qv.x, qv.x, reg2);
            reg1 += fabsf(qv.y); reg2 = fmaf(qv.y, qv.y, reg2);
            reg1 += fabsf(qv.z); reg2 = fmaf(qv.z, qv.z, reg2);
            reg1 += fabsf(qv.w); reg2 = fmaf(qv.w, qv.w, reg2);
            float* d = &buf[hofs + dsto[w]];
            d[0] = qv.x; d[1] = qv.y; d[2] = qv.z; d[3] = qv.w;
        }
        __syncthreads();

        if (s < NST - 1) {
            int nb = base4 + (s + 1) * 1600;
#pragma unroll
            for (int w = 0; w < 5; w++) v[w] = wp4[nb + tid + w * 320];
        }

        const char* bb = smem_raw + hofs * 4;
        const int pbase = q * 64 + s * 16;

        // Gather p>i: 2 accumulators (b0, b1), 16 tiles.
        if (pbase + TS - 1 > i) {
            const uint4 U0 = xpk4[s * 32 + b0];
            const uint4 U1 = xpk4[s * 32 + b1];
            const uint32_t w0[4] = {U0.x, U0.y, U0.z, U0.w};
            const uint32_t w1[4] = {U1.x, U1.y, U1.z, U1.w};
            const char* bj = bb + j84;
            if (pbase > i) {
#pragma unroll
                for (int k = 0; k < TS; k++) {
                    uint32_t e0 = __byte_perm(w0[k >> 2], 0, 0x4440 | (k & 3));
                    uint32_t e1 = __byte_perm(w1[k >> 2], 0, 0x4440 | (k & 3));
                    acc0 += *reinterpret_cast<const float*>(bj + k * 1680 + e0);
                    acc1 += *reinterpret_cast<const float*>(bj + k * 1680 + e1);
                }
            } else {
#pragma unroll
                for (int k = 0; k < TS; k++) {
                    if (pbase + k > i) {
                        uint32_t e0 = __byte_perm(w0[k >> 2], 0, 0x4440 | (k & 3));
                        uint32_t e1 = __byte_perm(w1[k >> 2], 0, 0x4440 | (k & 3));
                        acc0 += *reinterpret_cast<const float*>(bj + k * 1680 + e0);
                        acc1 += *reinterpret_cast<const float*>(bj + k * 1680 + e1);
                    }
                }
            }
        }

        // Pair energy: warp 0, lane = b, all 16 tiles.
        if (wid == 0) {
            const uint4 UP = xpk4[s * 32 + lane];
            const uint32_t wv[4] = {UP.x, UP.y, UP.z, UP.w};
            const char* bp = bb + xi84;
#pragma unroll
            for (int k = 0; k < TS; k++) {
                uint32_t e = __byte_perm(wv[k >> 2], 0, 0x4440 | (k & 3));
                pair += *reinterpret_cast<const float*>(bp + k * 1680 + e);
            }
        }

        // Const terms: warp 1, lanes 0..19 (j = lane).
        if (wid == 1 && lane < 20 && pbase <= i) {
            int tmax = i - pbase;               // t < tmax  <=>  p < i
            int lim = tmax < TS ? tmax : TS;
            const float* bt = reinterpret_cast<const float*>(bb);
            for (int t = 0; t < lim; t++) c_acc += bt[t * 420 + lane * 21 + 19];
            if (tmax >= 0 && tmax < TS) c_acc += bt[tmax * 420 + lane * 22];
        }
        // (next loop iteration's __syncthreads separates reuse of this half)
    }
    __syncthreads();

    // ---- Per-CTA epilogue: write quarter partials to global ----
    {
        float rv = reg1 + reg2;
#pragma unroll
        for (int o = 16; o > 0; o >>= 1) rv += __shfl_down_sync(0xffffffffu, rv, o);
        if (lane == 0) sredr[wid] = rv;
    }
    if (wid == 0) {
        float pv = pair;
#pragma unroll
        for (int o = 16; o > 0; o >>= 1) pv += __shfl_down_sync(0xffffffffu, pv, o);
        if (lane == 0) pairv[0] = pv;
    }
    __syncthreads();

    float* lg = &g_lg[i][q][0];
    lg[tid] = acc0;                 // index b0*20+j = tid
    lg[tid + 320] = acc1;           // index b1*20+j = tid+320
    if (wid == 1 && lane < 20) lg[640 + lane] = c_acc;
    if (tid == 0) {
        float rs = 0.f;
        for (int w = 0; w < 10; w++) rs += sredr[w];
        lg[660] = pairv[0];
        lg[661] = rs;
    }
    __threadfence();
    __syncthreads();

    // ---- Gate 1: 4th CTA of row i combines ----
    if (tid == 0) flags[0] = (atomicAdd(&g_icount[i], 1u) == 3u) ? 1 : 0;
    __syncthreads();
    if (!flags[0]) return;
    __threadfence();

    if (tid < 20) {
        csts[tid] = g_lg[i][0][640 + tid] + g_lg[i][1][640 + tid] +
                    g_lg[i][2][640 + tid] + g_lg[i][3][640 + tid];
    }
    __syncthreads();
    for (int n = tid; n < 640; n += NTHR) {
        float sv = g_lg[i][0][n] + g_lg[i][1][n] + g_lg[i][2][n] + g_lg[i][3][n];
        int bb2 = n / 20, jj = n - bb2 * 20;
        buf[bb2 * 21 + jj] = sv + csts[jj] + wsrow[jj];
    }
    if (tid == 300)
        g_res[i][1] = (double)g_lg[i][0][660] + (double)g_lg[i][1][660] +
                      (double)g_lg[i][2][660] + (double)g_lg[i][3][660];
    if (tid == 301)
        g_res[i][2] = (double)g_lg[i][0][661] + (double)g_lg[i][1][661] +
                      (double)g_lg[i][2][661] + (double)g_lg[i][3][661];
    __syncthreads();

    if (tid < 32) {       // lse per b, minus single
        const float* row = &buf[tid * 21];
        float m = row[0];
#pragma unroll
        for (int jj = 1; jj < A_; jj++) m = fmaxf(m, row[jj]);
        float se = 0.f;
#pragma unroll
        for (int jj = 0; jj < A_; jj++) se += __expf(row[jj] - m);
        float lse = m + __logf(se);
        double val = (double)lse - (double)wsrow[xi[tid]];
#pragma unroll
        for (int o = 16; o > 0; o >>= 1) val += __shfl_down_sync(0xffffffffu, val, o);
        if (tid == 0) g_res[i][0] = val;
    }
    __syncthreads();
    if (tid == 0) g_icount[i] = 0;   // self-reset for graph replay
    __threadfence();
    __syncthreads();

    // ---- Gate 2: last combiner does deterministic final reduction ----
    if (tid == 0) flags[1] = (atomicAdd(&g_bcount, 1u) == (unsigned)(L_ - 1)) ? 1 : 0;
    __syncthreads();
    if (!flags[1]) return;
    __threadfence();

    double LS = 0.0, PA = 0.0, RP = 0.0, RS = 0.0;
    if (tid < L_) { LS = g_res[tid][0]; PA = g_res[tid][1]; RP = g_res[tid][2]; }
    for (int n = tid; n < L_ * A_; n += NTHR) {
        float w = ws[n];
        RS += (double)fabsf(w) + (double)w * (double)w;
    }
    double* dred = reinterpret_cast<double*>(smem_raw + 4096);
#pragma unroll
    for (int o = 16; o > 0; o >>= 1) {
        LS += __shfl_down_sync(0xffffffffu, LS, o);
        PA += __shfl_down_sync(0xffffffffu, PA, o);
        RP += __shfl_down_sync(0xffffffffu, RP, o);
        RS += __shfl_down_sync(0xffffffffu, RS, o);
    }
    if (lane == 0) {
        dred[wid] = LS; dred[10 + wid] = PA; dred[20 + wid] = RP; dred[30 + wid] = RS;
    }
    __syncthreads();
    if (tid == 0) {
        double ls = 0, pa = 0, rp = 0, rs = 0;
        for (int w = 0; w < 10; w++) {
            ls += dred[w]; pa += dred[10 + w]; rp += dred[20 + w]; rs += dred[30 + w];
        }
        // LAMBDA_SINGLE = 1.0, LAMBDA_PAIR = 0.2*(L-1) = 51.0
        out[0] = (float)((ls - pa) / (double)B_ + 1.0 * rs + 51.0 * rp);
        g_bcount = 0;   // self-reset for graph replay
    }
}

extern "C" void kernel_launch(void* const* d_in, const int* in_sizes, int n_in,
                              void* d_out, int out_size) {
    (void)in_sizes; (void)n_in; (void)out_size;
    const int*   x  = (const int*)d_in[0];
    const float* ws = (const float*)d_in[1];
    const float* wp = (const float*)d_in[2];
    float* out = (float*)d_out;

    cudaFuncSetAttribute(mrf_kernel, cudaFuncAttributeMaxDynamicSharedMemorySize, SMEM_BYTES);
    dim3 grid(L_, 4);
    mrf_kernel<<<grid, NTHR, SMEM_BYTES>>>(x, ws, wp, out);
}

// round 12
// speedup vs baseline: 1.2119x; 1.2119x over previous
#include <cuda_runtime.h>
#include <math.h>
#include <stdint.h>

#define B_ 32
#define L_ 256
#define A_ 20
#define NTHR 384            // 10 consumer warps + pair/const warp + producer warp
#define TS 8                // tiles per stage
#define RING 4
#define NSTAGE 16           // 128 tiles per half-row / 8
#define STAGE_F 3200
#define STAGE_BYTES 12800

__device__ float g_lg[L_][2][662];        // per (i,h): 640 acc, 20 const, pair, reg
__device__ unsigned int g_icount[L_];     // per-i arrival counters (self-reset)
__device__ unsigned int g_bcount = 0;     // combiner counter (self-reset)
__device__ double g_res[L_][3];           // per-i {lse_sum, pair_sum, reg_sum}

// smem layout (bytes):
//   0     .. 51200  ring data (4 x 12800), row-major tiles
//   51200 .. 55296  xpk uint32[16 sidx][32 b][2 g]: bytes 4*x[b][p]
//   55296 .. 55424  xi[32]
//   55424 .. 55504  wsrow[20]
//   55504 .. 55552  sredr[12]
//   55552 .. 55556  pairv
//   55560 .. 55624  mbarriers per r (stride 16): full +0, empty +8
//   55624 .. 55632  flags[2]
// combiner reuse: lgbuf f32[32*21] @0, dred double[48] @4096
#define SMEM_BYTES 55632
#define MB_OFF 55560

__device__ __forceinline__ uint32_t smem_u32(const void* p) {
    uint32_t a;
    asm("{ .reg .u64 t; cvta.to.shared.u64 t, %1; cvt.u32.u64 %0, t; }" : "=r"(a) : "l"(p));
    return a;
}
#define MB_INIT(addr, cnt) \
    asm volatile("mbarrier.init.shared.b64 [%0], %1;" :: "r"(addr), "r"(cnt) : "memory")
#define MB_EXPECT_TX(addr, bytes) \
    asm volatile("mbarrier.arrive.expect_tx.shared.b64 _, [%0], %1;" :: "r"(addr), "r"(bytes) : "memory")
#define MB_ARRIVE(addr) \
    asm volatile("mbarrier.arrive.shared.b64 _, [%0];" :: "r"(addr) : "memory")

__device__ __forceinline__ void mb_wait_acq(uint32_t mbar, uint32_t parity) {
    asm volatile(
        "{\n\t.reg .pred P;\n\t"
        "WL_%=:\n\t"
        "mbarrier.try_wait.parity.acquire.cta.shared::cta.b64 P, [%0], %1, 0x989680;\n\t"
        "@P bra.uni WD_%=;\n\t"
        "bra.uni WL_%=;\n\t"
        "WD_%=:\n\t}"
        :: "r"(mbar), "r"(parity) : "memory");
}
__device__ __forceinline__ void mb_wait_rlx(uint32_t mbar, uint32_t parity) {
    asm volatile(
        "{\n\t.reg .pred P;\n\t"
        "WL_%=:\n\t"
        "mbarrier.try_wait.parity.relaxed.cta.shared::cta.b64 P, [%0], %1, 0x989680;\n\t"
        "@P bra.uni WD_%=;\n\t"
        "bra.uni WL_%=;\n\t"
        "WD_%=:\n\t}"
        :: "r"(mbar), "r"(parity) : "memory");
}
__device__ __forceinline__ void bulk_g2s(uint32_t dst, const void* src,
                                         uint32_t bytes, uint32_t mbar) {
    asm volatile(
        "cp.async.bulk.shared::cta.global.mbarrier::complete_tx::bytes [%0], [%1], %2, [%3];"
        :: "r"(dst), "l"(src), "r"(bytes), "r"(mbar) : "memory");
}

__global__ __launch_bounds__(NTHR, 4) void mrf_kernel(const int* __restrict__ x,
                                                      const float* __restrict__ ws,
                                                      const float* __restrict__ wp,
                                                      float* __restrict__ out) {
    extern __shared__ char smem_raw[];
    float*        bufs  = reinterpret_cast<float*>(smem_raw);
    uint32_t*     xpk   = reinterpret_cast<uint32_t*>(smem_raw + 51200);
    int*          xi    = reinterpret_cast<int*>(smem_raw + 55296);
    float*        wsrow = reinterpret_cast<float*>(smem_raw + 55424);
    float*        sredr = reinterpret_cast<float*>(smem_raw + 55504);
    float*        pairv = reinterpret_cast<float*>(smem_raw + 55552);
    int*          flags = reinterpret_cast<int*>(smem_raw + 55624);
    const uint32_t mb0  = smem_u32(smem_raw + MB_OFF);
    const uint32_t bufa = smem_u32(smem_raw);

    const int i    = blockIdx.x;
    const int h    = blockIdx.y;          // half: p in [h*128, h*128+128)
    const int tid  = threadIdx.x;
    const int wid  = tid >> 5;
    const int lane = tid & 31;

    // full: tx-based (count 1). empty: 11 arrivals (10 consumers + pair/const warp).
    if (tid == 0) {
        for (int r = 0; r < RING; r++) {
            MB_INIT(mb0 + r * 16, 1);
            MB_INIT(mb0 + r * 16 + 8, 11);
        }
    }

    // Pack x bytes (pre-scaled by 4): xpk[sidx*64 + b*2 + g] = bytes of
    // 4*x[b][p], p = h*128 + sidx*8 + 4g .. +3
    const int4* x4 = reinterpret_cast<const int4*>(x);
    for (int n = tid; n < 1024; n += NTHR) {
        int sidx = n >> 6, rem = n & 63;
        int b = rem >> 1, g = rem & 1;
        int4 q = x4[b * 64 + h * 32 + sidx * 2 + g];
        xpk[n] = (uint32_t)(q.x << 2) | ((uint32_t)(q.y << 2) << 8) |
                 ((uint32_t)(q.z << 2) << 16) | ((uint32_t)(q.w << 2) << 24);
    }
    if (tid < B_) xi[tid] = x[tid * L_ + i];
    if (tid >= 32 && tid < 52) wsrow[tid - 32] = ws[i * A_ + (tid - 32)];
    asm volatile("fence.proxy.async.shared::cta;" ::: "memory");
    __syncthreads();

    float acc0 = 0.f, acc1 = 0.f, pair = 0.f, c_acc = 0.f, reg1 = 0.f, reg2 = 0.f;

    if (wid < 10) {
        // ---- Consumers: warp = {j, j+10}, lane = b ----
        const char* btj0 = smem_raw + wid * 80;        // row j = wid
        const uint2* xpk2 = reinterpret_cast<const uint2*>(xpk);
        const float4* b4all = reinterpret_cast<const float4*>(smem_raw);
        const float2* b2all = reinterpret_cast<const float2*>(smem_raw);
        int r = 0, ph = 0;
        for (int sidx = 0; sidx < NSTAGE; sidx++) {
            mb_wait_acq(mb0 + r * 16, ph);

            // reg pass: 10 floats/lane (2 x LDS.128 + 1 x LDS.64)
            {
                float4 q1 = b4all[r * 800 + tid];
                float4 q2 = b4all[r * 800 + 320 + tid];
                float2 t2 = b2all[r * 1600 + 1280 + tid];
                reg1 += fabsf(q1.x); reg2 = fmaf(q1.x, q1.x, reg2);
                reg1 += fabsf(q1.y); reg2 = fmaf(q1.y, q1.y, reg2);
                reg1 += fabsf(q1.z); reg2 = fmaf(q1.z, q1.z, reg2);
                reg1 += fabsf(q1.w); reg2 = fmaf(q1.w, q1.w, reg2);
                reg1 += fabsf(q2.x); reg2 = fmaf(q2.x, q2.x, reg2);
                reg1 += fabsf(q2.y); reg2 = fmaf(q2.y, q2.y, reg2);
                reg1 += fabsf(q2.z); reg2 = fmaf(q2.z, q2.z, reg2);
                reg1 += fabsf(q2.w); reg2 = fmaf(q2.w, q2.w, reg2);
                reg1 += fabsf(t2.x); reg2 = fmaf(t2.x, t2.x, reg2);
                reg1 += fabsf(t2.y); reg2 = fmaf(t2.y, t2.y, reg2);
            }

            const int pbase = h * 128 + sidx * TS;
            if (pbase + TS - 1 > i) {
                const char* bj = btj0 + r * STAGE_BYTES;
                const uint2 u = xpk2[sidx * 32 + lane];
                const uint32_t wv[2] = {u.x, u.y};
                if (pbase > i) {          // ABOVE: all 8 tiles
#pragma unroll
                    for (int k = 0; k < TS; k++) {
                        uint32_t e4 = __byte_perm(wv[k >> 2], 0, 0x4440 | (k & 3));
                        acc0 += *reinterpret_cast<const float*>(bj + k * 1600 + e4);
                        acc1 += *reinterpret_cast<const float*>(bj + k * 1600 + 800 + e4);
                    }
                } else {                  // MIXED
#pragma unroll
                    for (int k = 0; k < TS; k++) {
                        if (pbase + k > i) {
                            uint32_t e4 = __byte_perm(wv[k >> 2], 0, 0x4440 | (k & 3));
                            acc0 += *reinterpret_cast<const float*>(bj + k * 1600 + e4);
                            acc1 += *reinterpret_cast<const float*>(bj + k * 1600 + 800 + e4);
                        }
                    }
                }
            }
            if (lane == 0) MB_ARRIVE(mb0 + r * 16 + 8);
            if (++r == RING) { r = 0; ph ^= 1; }
        }
    } else if (wid == 10) {
        // ---- Pair (all lanes, b = lane) + const (lanes 0..19, j = lane) warp ----
        const char* bt0 = smem_raw + xi[lane] * 80;
        const uint2* xpk2 = reinterpret_cast<const uint2*>(xpk);
        const int j20 = lane * 20;
        int r = 0, ph = 0;
        for (int sidx = 0; sidx < NSTAGE; sidx++) {
            mb_wait_acq(mb0 + r * 16, ph);
            const char* bt = bt0 + r * STAGE_BYTES;
            const uint2 u = xpk2[sidx * 32 + lane];
            const uint32_t wv[2] = {u.x, u.y};
#pragma unroll
            for (int k = 0; k < TS; k++) {
                uint32_t e4 = __byte_perm(wv[k >> 2], 0, 0x4440 | (k & 3));
                pair += *reinterpret_cast<const float*>(bt + k * 1600 + e4);
            }
            const int pbase = h * 128 + sidx * TS;
            if (lane < 20 && pbase <= i) {
                const float* bf = bufs + r * STAGE_F;
                int tmax = i - pbase;              // t < tmax  <=>  p < i
                int lim = tmax < TS ? tmax : TS;
                for (int t = 0; t < lim; t++) c_acc += bf[t * 400 + j20 + 19];
                if (tmax < TS) c_acc += bf[tmax * 400 + j20 + lane];   // diag p==i
            }
            if (lane == 0) MB_ARRIVE(mb0 + r * 16 + 8);
            if (++r == RING) { r = 0; ph ^= 1; }
        }
    } else {
        // ---- Producer (warp 11, lane 0) ----
        if (lane == 0) {
            const char* src = reinterpret_cast<const char*>(wp) +
                              (size_t)i * 409600 + (size_t)h * 204800;
            int r = 0, wr = 0, wph = 0;
            for (int sidx = 0; sidx < NSTAGE; sidx++) {
                if (sidx >= RING) {
                    mb_wait_rlx(mb0 + wr * 16 + 8, wph);
                    if (++wr == RING) { wr = 0; wph ^= 1; }
                }
                MB_EXPECT_TX(mb0 + r * 16, STAGE_BYTES);
                bulk_g2s(bufa + r * STAGE_BYTES, src + (size_t)sidx * STAGE_BYTES,
                         STAGE_BYTES, mb0 + r * 16);
                if (++r == RING) r = 0;
            }
        }
    }

    // ---------------- Per-CTA epilogue: write half-row partials ----------------
    if (wid < 10) {
        float rv = reg1 + reg2;
#pragma unroll
        for (int o = 16; o > 0; o >>= 1) rv += __shfl_down_sync(0xffffffffu, rv, o);
        if (lane == 0) sredr[wid] = rv;
    }
    if (wid == 10) {
        float pv = pair;
#pragma unroll
        for (int o = 16; o > 0; o >>= 1) pv += __shfl_down_sync(0xffffffffu, pv, o);
        if (lane == 0) pairv[0] = pv;
    }
    __syncthreads();

    float* lg = &g_lg[i][h][0];
    if (wid < 10) {
        lg[lane * 20 + wid] = acc0;
        lg[lane * 20 + wid + 10] = acc1;
    }
    if (wid == 10 && lane < 20) lg[640 + lane] = c_acc;
    if (tid == 352) {
        float rs = 0.f;
        for (int w = 0; w < 10; w++) rs += sredr[w];
        lg[660] = pairv[0];
        lg[661] = rs;
    }
    __threadfence();
    __syncthreads();

    // ---- Gate 1: 2nd CTA of row i combines ----
    if (tid == 0) flags[0] = (atomicAdd(&g_icount[i], 1u) == 1u) ? 1 : 0;
    __syncthreads();
    if (!flags[0]) return;
    __threadfence();

    for (int n = tid; n < 640; n += NTHR) {
        float sv = g_lg[i][0][n] + g_lg[i][1][n];
        int bb = n / 20, jj = n - bb * 20;
        bufs[bb * 21 + jj] = sv + (g_lg[i][0][640 + jj] + g_lg[i][1][640 + jj]) + wsrow[jj];
    }
    if (tid == 352) g_res[i][1] = (double)g_lg[i][0][660] + (double)g_lg[i][1][660];
    if (tid == 353) g_res[i][2] = (double)g_lg[i][0][661] + (double)g_lg[i][1][661];
    __syncthreads();

    if (tid < 32) {       // lse per b, minus single
        const float* row = &bufs[tid * 21];
        float m = row[0];
#pragma unroll
        for (int jj = 1; jj < A_; jj++) m = fmaxf(m, row[jj]);
        float se = 0.f;
#pragma unroll
        for (int jj = 0; jj < A_; jj++) se += __expf(row[jj] - m);
        float lse = m + __logf(se);
        double val = (double)lse - (double)wsrow[xi[tid]];
#pragma unroll
        for (int o = 16; o > 0; o >>= 1) val += __shfl_down_sync(0xffffffffu, val, o);
        if (tid == 0) g_res[i][0] = val;
    }
    __syncthreads();
    if (tid == 0) g_icount[i] = 0;   // self-reset for graph replay
    __threadfence();
    __syncthreads();

    // ---- Gate 2: last combiner does deterministic final reduction ----
    if (tid == 0) flags[1] = (atomicAdd(&g_bcount, 1u) == (unsigned)(L_ - 1)) ? 1 : 0;
    __syncthreads();
    if (!flags[1]) return;
    __threadfence();

    double LS = 0.0, PA = 0.0, RP = 0.0, RS = 0.0;
    if (tid < L_) { LS = g_res[tid][0]; PA = g_res[tid][1]; RP = g_res[tid][2]; }
    for (int n = tid; n < L_ * A_; n += NTHR) {
        float w = ws[n];
        RS += (double)fabsf(w) + (double)w * (double)w;
    }
    double* dred = reinterpret_cast<double*>(smem_raw + 4096);
#pragma unroll
    for (int o = 16; o > 0; o >>= 1) {
        LS += __shfl_down_sync(0xffffffffu, LS, o);
        PA += __shfl_down_sync(0xffffffffu, PA, o);
        RP += __shfl_down_sync(0xffffffffu, RP, o);
        RS += __shfl_down_sync(0xffffffffu, RS, o);
    }
    if (lane == 0) {
        dred[wid] = LS; dred[12 + wid] = PA; dred[24 + wid] = RP; dred[36 + wid] = RS;
    }
    __syncthreads();
    if (tid == 0) {
        double ls = 0, pa = 0, rp = 0, rs = 0;
        for (int w = 0; w < 12; w++) {
            ls += dred[w]; pa += dred[12 + w]; rp += dred[24 + w]; rs += dred[36 + w];
        }
        // LAMBDA_SINGLE = 1.0, LAMBDA_PAIR = 0.2*(L-1) = 51.0
        out[0] = (float)((ls - pa) / (double)B_ + 1.0 * rs + 51.0 * rp);
        g_bcount = 0;   // self-reset for graph replay
    }
}

extern "C" void kernel_launch(void* const* d_in, const int* in_sizes, int n_in,
                              void* d_out, int out_size) {
    (void)in_sizes; (void)n_in; (void)out_size;
    const int*   x  = (const int*)d_in[0];
    const float* ws = (const float*)d_in[1];
    const float* wp = (const float*)d_in[2];
    float* out = (float*)d_out;

    cudaFuncSetAttribute(mrf_kernel, cudaFuncAttributeMaxDynamicSharedMemorySize, SMEM_BYTES);
    dim3 grid(L_, 2);
    mrf_kernel<<<grid, NTHR, SMEM_BYTES>>>(x, ws, wp, out);
}